// round 3
// baseline (speedup 1.0000x reference)
#include <cuda_runtime.h>
#include <cuda_bf16.h>

// Problem constants (V=50000, E=800000, D=H=128)
#define VMAX 50048
#define EMAX 800000

// Scratch (device globals: allocation-free rule)
__device__ float g_hv[VMAX * 128];   // projected node feats
__device__ float g_pd[VMAX];         // dst-half edge logit scalar per node
__device__ float g_ps[VMAX];         // src-half edge logit scalar per node
__device__ float g_sx[VMAX];         // sum of exp(logit) per dst node
__device__ float g_ew[EMAX];         // exp(logit) per edge
__device__ float g_c [VMAX * 128];   // aggregated context (pre-elu)
__device__ float g_g1[VMAX * 384];   // gi = elu(c) @ W_ih^T + b_ih
__device__ float g_g2[VMAX * 384];   // gh = nf @ W_hh^T + b_hh

// ---------------------------------------------------------------------------
// Zero accumulators (c and s) each call
__global__ void zero_kernel(int V) {
    int i = blockIdx.x * blockDim.x + threadIdx.x;
    int n = V * 128;
    if (i < n) g_c[i] = 0.0f;
    if (i < V) g_sx[i] = 0.0f;
}

// ---------------------------------------------------------------------------
// Per-node scalars pd, ps  (warp per node, rank-1 W_edge trick)
__global__ void pnode_kernel(const float* __restrict__ nf,
                             const float* __restrict__ We, int V) {
    int w    = (blockIdx.x * blockDim.x + threadIdx.x) >> 5;
    int lane = threadIdx.x & 31;
    if (w >= V) return;
    float4 x  = ((const float4*)nf)[w * 32 + lane];
    float4 w1 = ((const float4*)We)[lane];        // We[0:128]
    float4 w2 = ((const float4*)We)[32 + lane];   // We[128:256]
    float pd = x.x * w1.x + x.y * w1.y + x.z * w1.z + x.w * w1.w;
    float ps = x.x * w2.x + x.y * w2.y + x.z * w2.z + x.w * w2.w;
    #pragma unroll
    for (int o = 16; o; o >>= 1) {
        pd += __shfl_xor_sync(0xFFFFFFFFu, pd, o);
        ps += __shfl_xor_sync(0xFFFFFFFFu, ps, o);
    }
    if (lane == 0) { g_pd[w] = pd; g_ps[w] = ps; }
}

// ---------------------------------------------------------------------------
// Per-edge exp(leaky_relu(logit)); accumulate denominator per dst.
// Max-subtraction is skipped: softmax is shift-invariant and logits are small.
__global__ void edge_kernel(const int* __restrict__ src,
                            const int* __restrict__ dst,
                            const float* __restrict__ b_edge, int E) {
    int e = blockIdx.x * blockDim.x + threadIdx.x;
    if (e >= E) return;
    int d = dst[e], s = src[e];
    float x = g_pd[d] + g_ps[s] + b_edge[0];
    x = (x >= 0.0f) ? x : 0.01f * x;       // LeakyReLU(0.01)
    float w = expf(x);
    g_ew[e] = w;
    atomicAdd(&g_sx[d], w);
}

// ---------------------------------------------------------------------------
// Scatter: c[dst] += hv[src] * (ew/s[dst]).  Warp per edge, v4 reductions.
__global__ void scatter_kernel(const int* __restrict__ src,
                               const int* __restrict__ dst, int E) {
    int w    = (blockIdx.x * blockDim.x + threadIdx.x) >> 5;
    int lane = threadIdx.x & 31;
    if (w >= E) return;
    int d = dst[w], s = src[w];
    float a = g_ew[w] / g_sx[d];
    float4 v = ((const float4*)g_hv)[s * 32 + lane];
    float* p = &g_c[d * 128 + lane * 4];
    asm volatile("red.global.add.v4.f32 [%0], {%1,%2,%3,%4};"
                 :: "l"(p), "f"(v.x * a), "f"(v.y * a), "f"(v.z * a), "f"(v.w * a)
                 : "memory");
}

// ---------------------------------------------------------------------------
// SGEMM: C[M,Ntot](bn tile) = A[M,128] @ B[Ntot,128]^T + bias
// amode=1: apply elu to A elements on load (context path).
// 128x128 block tile, K=128 in 4 chunks of 32, 8x8 register micro-tile.
__global__ __launch_bounds__(256)
void gemm_k128(const float* __restrict__ A, const float* __restrict__ B,
               const float* __restrict__ bias, float* __restrict__ C,
               int M, int Ntot, int amode) {
    __shared__ float As[32][132];
    __shared__ float Bs[32][132];
    int tid = threadIdx.x;
    int bm = blockIdx.x * 128;
    int bn = blockIdx.y * 128;
    int tm = (tid >> 4) << 3;   // 0..120 step 8
    int tn = (tid & 15) << 3;   // 0..120 step 8

    float acc[8][8];
    #pragma unroll
    for (int i = 0; i < 8; i++)
        #pragma unroll
        for (int j = 0; j < 8; j++) acc[i][j] = 0.0f;

    for (int k0 = 0; k0 < 128; k0 += 32) {
        #pragma unroll
        for (int i = 0; i < 4; i++) {
            int t   = tid + i * 256;   // 0..1023 float4 slots
            int row = t >> 3;          // 0..127
            int c4  = t & 7;           // float4 index within 32-K chunk
            int gr  = bm + row;
            float4 v = make_float4(0.f, 0.f, 0.f, 0.f);
            if (gr < M) v = *(const float4*)&A[gr * 128 + k0 + c4 * 4];
            if (amode) {   // elu
                v.x = v.x > 0.f ? v.x : expm1f(v.x);
                v.y = v.y > 0.f ? v.y : expm1f(v.y);
                v.z = v.z > 0.f ? v.z : expm1f(v.z);
                v.w = v.w > 0.f ? v.w : expm1f(v.w);
            }
            As[c4 * 4 + 0][row] = v.x;
            As[c4 * 4 + 1][row] = v.y;
            As[c4 * 4 + 2][row] = v.z;
            As[c4 * 4 + 3][row] = v.w;
            float4 u = *(const float4*)&B[(bn + row) * 128 + k0 + c4 * 4];
            Bs[c4 * 4 + 0][row] = u.x;
            Bs[c4 * 4 + 1][row] = u.y;
            Bs[c4 * 4 + 2][row] = u.z;
            Bs[c4 * 4 + 3][row] = u.w;
        }
        __syncthreads();
        #pragma unroll
        for (int kk = 0; kk < 32; kk++) {
            float4 a0 = *(const float4*)&As[kk][tm];
            float4 a1 = *(const float4*)&As[kk][tm + 4];
            float4 b0 = *(const float4*)&Bs[kk][tn];
            float4 b1 = *(const float4*)&Bs[kk][tn + 4];
            float av[8] = {a0.x, a0.y, a0.z, a0.w, a1.x, a1.y, a1.z, a1.w};
            float bv[8] = {b0.x, b0.y, b0.z, b0.w, b1.x, b1.y, b1.z, b1.w};
            #pragma unroll
            for (int i = 0; i < 8; i++)
                #pragma unroll
                for (int j = 0; j < 8; j++)
                    acc[i][j] += av[i] * bv[j];
        }
        __syncthreads();
    }
    #pragma unroll
    for (int i = 0; i < 8; i++) {
        int gr = bm + tm + i;
        if (gr >= M) continue;
        #pragma unroll
        for (int j = 0; j < 8; j += 4) {
            float4 o;
            o.x = acc[i][j + 0] + bias[bn + tn + j + 0];
            o.y = acc[i][j + 1] + bias[bn + tn + j + 1];
            o.z = acc[i][j + 2] + bias[bn + tn + j + 2];
            o.w = acc[i][j + 3] + bias[bn + tn + j + 3];
            *(float4*)&C[gr * Ntot + bn + tn + j] = o;
        }
    }
}

// ---------------------------------------------------------------------------
// GRU gates + ReLU (fully elementwise at (v,d))
__global__ void gates_kernel(const float* __restrict__ nf,
                             float* __restrict__ out, int V) {
    int i = blockIdx.x * blockDim.x + threadIdx.x;
    if (i >= V * 128) return;
    int v = i >> 7, d = i & 127;
    const float* r1 = &g_g1[v * 384];
    const float* r2 = &g_g2[v * 384];
    float r = 1.0f / (1.0f + expf(-(r1[d]       + r2[d])));
    float z = 1.0f / (1.0f + expf(-(r1[128 + d] + r2[128 + d])));
    float n = tanhf(r1[256 + d] + r * r2[256 + d]);
    float h = (1.0f - z) * n + z * nf[i];
    out[i] = h > 0.0f ? h : 0.0f;
}

// ---------------------------------------------------------------------------
extern "C" void kernel_launch(void* const* d_in, const int* in_sizes, int n_in,
                              void* d_out, int out_size) {
    const float* nf     = (const float*)d_in[0];
    const float* W_edge = (const float*)d_in[1];
    const float* b_edge = (const float*)d_in[2];
    const float* W_proj = (const float*)d_in[3];
    const float* b_proj = (const float*)d_in[4];
    const float* W_ih   = (const float*)d_in[5];
    const float* W_hh   = (const float*)d_in[6];
    const float* b_ih   = (const float*)d_in[7];
    const float* b_hh   = (const float*)d_in[8];
    const int*   src    = (const int*)d_in[9];
    const int*   dst    = (const int*)d_in[10];

    int V = in_sizes[0] / 128;
    int E = in_sizes[9];
    if (V > VMAX) V = VMAX;
    if (E > EMAX) E = EMAX;

    float *hv, *c, *g1, *g2;
    cudaGetSymbolAddress((void**)&hv, g_hv);
    cudaGetSymbolAddress((void**)&c,  g_c);
    cudaGetSymbolAddress((void**)&g1, g_g1);
    cudaGetSymbolAddress((void**)&g2, g_g2);

    int mb = (V + 127) / 128;

    // 1. zero c, s
    zero_kernel<<<(V * 128 + 255) / 256, 256>>>(V);
    // 2. hv = nf @ W_proj^T + b_proj
    gemm_k128<<<dim3(mb, 1), 256>>>(nf, W_proj, b_proj, hv, V, 128, 0);
    // 3. per-node edge-logit scalars
    pnode_kernel<<<(V * 32 + 255) / 256, 256>>>(nf, W_edge, V);
    // 4. per-edge softmax numerator + denominator
    edge_kernel<<<(E + 255) / 256, 256>>>(src, dst, b_edge, E);
    // 5. weighted aggregation into c
    scatter_kernel<<<(E * 32 + 255) / 256, 256>>>(src, dst, E);
    // 6. gi = elu(c) @ W_ih^T + b_ih
    gemm_k128<<<dim3(mb, 3), 256>>>(c, W_ih, b_ih, g1, V, 384, 1);
    // 7. gh = nf @ W_hh^T + b_hh
    gemm_k128<<<dim3(mb, 3), 256>>>(nf, W_hh, b_hh, g2, V, 384, 0);
    // 8. gates + relu -> out
    gates_kernel<<<(V * 128 + 255) / 256, 256>>>(nf, (float*)d_out, V);
}